// round 2
// baseline (speedup 1.0000x reference)
#include <cuda_runtime.h>

#define BATCH 4
#define SEQ   4096
#define EMB   384
#define HDIM  64
#define BM    32              // query rows per tile
#define BN    32              // key rows per tile
#define NT    (SEQ / BM)      // 128 query tiles per batch
#define PAIRS (NT / 2)        // 64

__device__ float g_q[BATCH * SEQ * HDIM];
__device__ float g_k[BATCH * SEQ * HDIM];
__device__ float g_v[BATCH * SEQ * HDIM];

// ---------------- fused QKV projection ----------------
// grid: (BATCH*SEQ)/16 blocks, 192 threads (thread t: matrix t/64, column t%64)
__global__ __launch_bounds__(192) void qkv_proj(const float* __restrict__ x,
                                                const float* __restrict__ Wq,
                                                const float* __restrict__ Wk,
                                                const float* __restrict__ Wv) {
    __shared__ float4 xs4[16 * 96];     // 16 rows x 384 floats
    const int tid = threadIdx.x;
    const size_t row0 = (size_t)blockIdx.x * 16;

    // cooperative load of 16 rows of x (1536 float4, coalesced)
    const float4* xsrc = (const float4*)(x + row0 * EMB);
#pragma unroll
    for (int i = 0; i < 8; i++) xs4[tid + i * 192] = xsrc[tid + i * 192];
    __syncthreads();

    const int mat = tid >> 6;
    const int col = tid & 63;
    const float* W = (mat == 0) ? Wq : (mat == 1 ? Wk : Wv);
    float* dst     = (mat == 0) ? g_q : (mat == 1 ? g_k : g_v);

    float acc[16];
#pragma unroll
    for (int r = 0; r < 16; r++) acc[r] = 0.f;

#pragma unroll 4
    for (int e4 = 0; e4 < 96; e4++) {
        const float w0 = W[(e4 * 4 + 0) * HDIM + col];
        const float w1 = W[(e4 * 4 + 1) * HDIM + col];
        const float w2 = W[(e4 * 4 + 2) * HDIM + col];
        const float w3 = W[(e4 * 4 + 3) * HDIM + col];
#pragma unroll
        for (int r = 0; r < 16; r++) {
            const float4 xv = xs4[r * 96 + e4];   // broadcast across warp
            acc[r] = fmaf(xv.x, w0, fmaf(xv.y, w1, fmaf(xv.z, w2, fmaf(xv.w, w3, acc[r]))));
        }
    }
#pragma unroll
    for (int r = 0; r < 16; r++)
        dst[(row0 + r) * HDIM + col] = acc[r];
}

// ---------------- causal flash attention (fp32) ----------------
// 128 threads: row = tid>>2 (32 rows), quad lane hq = tid&3 owns head dims [hq*16, hq*16+16)
// Each block processes query tiles (NT-1-pair) and (pair): equal work per block.
__global__ __launch_bounds__(128) void flash_fwd(float* __restrict__ out) {
    __shared__ float Ks[BN * HDIM];
    __shared__ float Vs[BN * HDIM];

    const int tid  = threadIdx.x;
    const int b    = blockIdx.x / PAIRS;
    const int pair = blockIdx.x % PAIRS;
    const int r    = tid >> 2;
    const int hq   = tid & 3;
    const float NEG_INF = __int_as_float(0xff800000);
    const float sm_scale = 0.125f;   // 1/sqrt(64)
    const size_t base = (size_t)b * SEQ * HDIM;

    for (int which = 0; which < 2; which++) {
        const int qt   = (which == 0) ? (NT - 1 - pair) : pair;
        const int qrow = qt * BM + r;

        // load q slice (16 floats) into registers
        float q[16];
        {
            const float4* qp = (const float4*)(g_q + base + (size_t)qrow * HDIM + hq * 16);
            float4 qv[4];
#pragma unroll
            for (int i = 0; i < 4; i++) qv[i] = qp[i];
#pragma unroll
            for (int i = 0; i < 4; i++) {
                q[4 * i + 0] = qv[i].x; q[4 * i + 1] = qv[i].y;
                q[4 * i + 2] = qv[i].z; q[4 * i + 3] = qv[i].w;
            }
        }

        float o[16];
#pragma unroll
        for (int i = 0; i < 16; i++) o[i] = 0.f;
        float m = NEG_INF, l = 0.f;

        const int nkt = qt + 1;
        for (int kt = 0; kt < nkt; kt++) {
            __syncthreads();
            {
                const float4* ksrc = (const float4*)(g_k + base + (size_t)kt * BN * HDIM);
                const float4* vsrc = (const float4*)(g_v + base + (size_t)kt * BN * HDIM);
                float4* Ks4 = (float4*)Ks;
                float4* Vs4 = (float4*)Vs;
#pragma unroll
                for (int i = 0; i < 4; i++) {
                    Ks4[tid + i * 128] = ksrc[tid + i * 128];
                    Vs4[tid + i * 128] = vsrc[tid + i * 128];
                }
            }
            __syncthreads();

            // scores for 32 keys
            float s[BN];
#pragma unroll
            for (int j = 0; j < BN; j++) {
                const float4* kr = (const float4*)(Ks + j * HDIM + hq * 16);
                float4 kv[4];
#pragma unroll
                for (int i = 0; i < 4; i++) kv[i] = kr[i];
                float a[4];
#pragma unroll
                for (int i = 0; i < 4; i++) {
                    a[i] = fmaf(q[4 * i + 0], kv[i].x,
                           fmaf(q[4 * i + 1], kv[i].y,
                           fmaf(q[4 * i + 2], kv[i].z,
                                q[4 * i + 3] * kv[i].w)));
                }
                float acc = (a[0] + a[1]) + (a[2] + a[3]);
                acc += __shfl_xor_sync(0xffffffffu, acc, 1);
                acc += __shfl_xor_sync(0xffffffffu, acc, 2);
                s[j] = acc * sm_scale;
            }

            if (kt == qt) {   // diagonal tile: causal mask
#pragma unroll
                for (int j = 0; j < BN; j++)
                    if (kt * BN + j > qrow) s[j] = NEG_INF;
            }

            float tmax = s[0];
#pragma unroll
            for (int j = 1; j < BN; j++) tmax = fmaxf(tmax, s[j]);
            const float mnew  = fmaxf(m, tmax);
            const float alpha = __expf(m - mnew);   // 0 on first tile (m = -inf)
            l *= alpha;
#pragma unroll
            for (int i = 0; i < 16; i++) o[i] *= alpha;

#pragma unroll
            for (int j = 0; j < BN; j++) {
                const float p = __expf(s[j] - mnew);
                l += p;
                const float4* vr = (const float4*)(Vs + j * HDIM + hq * 16);
                float4 vv[4];
#pragma unroll
                for (int i = 0; i < 4; i++) vv[i] = vr[i];
#pragma unroll
                for (int i = 0; i < 4; i++) {
                    o[4 * i + 0] = fmaf(p, vv[i].x, o[4 * i + 0]);
                    o[4 * i + 1] = fmaf(p, vv[i].y, o[4 * i + 1]);
                    o[4 * i + 2] = fmaf(p, vv[i].z, o[4 * i + 2]);
                    o[4 * i + 3] = fmaf(p, vv[i].w, o[4 * i + 3]);
                }
            }
            m = mnew;
        }

        const float inv = __fdividef(1.f, l);
        float4* op = (float4*)(out + base + (size_t)qrow * HDIM + hq * 16);
#pragma unroll
        for (int i = 0; i < 4; i++) {
            float4 ov;
            ov.x = o[4 * i + 0] * inv; ov.y = o[4 * i + 1] * inv;
            ov.z = o[4 * i + 2] * inv; ov.w = o[4 * i + 3] * inv;
            op[i] = ov;
        }
    }
}

extern "C" void kernel_launch(void* const* d_in, const int* in_sizes, int n_in,
                              void* d_out, int out_size) {
    const float* x  = (const float*)d_in[0];
    const float* Wq = (const float*)d_in[1];
    const float* Wk = (const float*)d_in[2];
    const float* Wv = (const float*)d_in[3];
    float* out = (float*)d_out;

    qkv_proj<<<(BATCH * SEQ) / 16, 192>>>(x, Wq, Wk, Wv);
    flash_fwd<<<BATCH * PAIRS, 128>>>(out);
}

// round 3
// speedup vs baseline: 1.7675x; 1.7675x over previous
#include <cuda_runtime.h>

#define BATCH 4
#define SEQ   4096
#define EMB   384
#define HDIM  64
#define BM    32
#define BN    32
#define NT    (SEQ / BM)      // 128
#define PAIRS (NT / 2)        // 64

__device__ float g_q[BATCH * SEQ * HDIM];
__device__ float g_k[BATCH * SEQ * HDIM];
__device__ float g_v[BATCH * SEQ * HDIM];

// ---------------- fused QKV projection (unchanged) ----------------
__global__ __launch_bounds__(192) void qkv_proj(const float* __restrict__ x,
                                                const float* __restrict__ Wq,
                                                const float* __restrict__ Wk,
                                                const float* __restrict__ Wv) {
    __shared__ float4 xs4[16 * 96];
    const int tid = threadIdx.x;
    const size_t row0 = (size_t)blockIdx.x * 16;

    const float4* xsrc = (const float4*)(x + row0 * EMB);
#pragma unroll
    for (int i = 0; i < 8; i++) xs4[tid + i * 192] = xsrc[tid + i * 192];
    __syncthreads();

    const int mat = tid >> 6;
    const int col = tid & 63;
    const float* W = (mat == 0) ? Wq : (mat == 1 ? Wk : Wv);
    float* dst     = (mat == 0) ? g_q : (mat == 1 ? g_k : g_v);

    float acc[16];
#pragma unroll
    for (int r = 0; r < 16; r++) acc[r] = 0.f;

#pragma unroll 4
    for (int e4 = 0; e4 < 96; e4++) {
        const float w0 = W[(e4 * 4 + 0) * HDIM + col];
        const float w1 = W[(e4 * 4 + 1) * HDIM + col];
        const float w2 = W[(e4 * 4 + 2) * HDIM + col];
        const float w3 = W[(e4 * 4 + 3) * HDIM + col];
#pragma unroll
        for (int r = 0; r < 16; r++) {
            const float4 xv = xs4[r * 96 + e4];
            acc[r] = fmaf(xv.x, w0, fmaf(xv.y, w1, fmaf(xv.z, w2, fmaf(xv.w, w3, acc[r]))));
        }
    }
#pragma unroll
    for (int r = 0; r < 16; r++)
        dst[(row0 + r) * HDIM + col] = acc[r];
}

// ---------------- register-tiled causal flash attention ----------------
// 128 threads = 16 trow x 8 tcol. Thread owns rows (2*trow, 2*trow+1).
// S phase: 2 rows x 4 cols (cols tcol*4..+4). PV phase: 2 rows x 8 dims (dims tcol*8..+8).
__global__ __launch_bounds__(128) void flash_fwd(float* __restrict__ out) {
    __shared__ float Qs[HDIM][36];   // transposed, pad 36 (16B aligned rows)
    __shared__ float Ks[HDIM][36];   // transposed
    __shared__ float Vs[BN][68];     // row-major, pad 68
    __shared__ float Ps[BN][34];     // [s][row], pad 34

    const int tid  = threadIdx.x;
    const int b    = blockIdx.x / PAIRS;
    const int pair = blockIdx.x % PAIRS;
    const int trow = tid >> 3;        // 0..15
    const int tcol = tid & 7;         // 0..7
    const int r0   = trow * 2;
    const int lrow = tid >> 2;        // 0..31 (loader row)
    const int lc4  = tid & 3;         // loader chunk
    const float NEG_INF  = __int_as_float(0xff800000);
    const float sm_scale = 0.125f;
    const size_t base = (size_t)b * SEQ * HDIM;

    for (int which = 0; which < 2; which++) {
        const int qt = which ? pair : (NT - 1 - pair);

        __syncthreads();   // previous iteration done with Qs
        // stage Q tile transposed
        {
            const float4* qsrc = (const float4*)(g_q + base + (size_t)(qt * BM) * HDIM);
#pragma unroll
            for (int j = 0; j < 4; j++) {
                float4 v = qsrc[lrow * 16 + lc4 + 4 * j];
                int d = (lc4 + 4 * j) * 4;
                Qs[d + 0][lrow] = v.x; Qs[d + 1][lrow] = v.y;
                Qs[d + 2][lrow] = v.z; Qs[d + 3][lrow] = v.w;
            }
        }

        float o[2][8];
#pragma unroll
        for (int i = 0; i < 2; i++)
#pragma unroll
            for (int d = 0; d < 8; d++) o[i][d] = 0.f;
        float m[2] = {NEG_INF, NEG_INF};
        float l[2] = {0.f, 0.f};

        const int nkt = qt + 1;

        // prefetch tile 0 into registers
        float4 kr[4], vr[4];
        {
            const float4* ksrc = (const float4*)(g_k + base + (size_t)(0 * BN) * HDIM);
            const float4* vsrc = (const float4*)(g_v + base + (size_t)(0 * BN) * HDIM);
#pragma unroll
            for (int j = 0; j < 4; j++) {
                kr[j] = ksrc[lrow * 16 + lc4 + 4 * j];
                vr[j] = vsrc[lrow * 16 + lc4 + 4 * j];
            }
        }

        for (int kt = 0; kt < nkt; kt++) {
            __syncthreads();   // all readers done with Ks/Vs/Ps
            // commit staged tile to shared
#pragma unroll
            for (int j = 0; j < 4; j++) {
                int d = (lc4 + 4 * j) * 4;
                Ks[d + 0][lrow] = kr[j].x; Ks[d + 1][lrow] = kr[j].y;
                Ks[d + 2][lrow] = kr[j].z; Ks[d + 3][lrow] = kr[j].w;
                *(float4*)&Vs[lrow][(lc4 + 4 * j) * 4] = vr[j];
            }
            __syncthreads();

            // prefetch next tile while computing this one
            if (kt + 1 < nkt) {
                const float4* ksrc = (const float4*)(g_k + base + (size_t)((kt + 1) * BN) * HDIM);
                const float4* vsrc = (const float4*)(g_v + base + (size_t)((kt + 1) * BN) * HDIM);
#pragma unroll
                for (int j = 0; j < 4; j++) {
                    kr[j] = ksrc[lrow * 16 + lc4 + 4 * j];
                    vr[j] = vsrc[lrow * 16 + lc4 + 4 * j];
                }
            }

            // ---- S = Q K^T (outer product over k) ----
            float s[2][4];
#pragma unroll
            for (int i = 0; i < 2; i++)
#pragma unroll
                for (int j = 0; j < 4; j++) s[i][j] = 0.f;

#pragma unroll 16
            for (int k = 0; k < HDIM; k++) {
                const float2 q2 = *(const float2*)&Qs[k][r0];
                const float4 k4 = *(const float4*)&Ks[k][tcol * 4];
                s[0][0] = fmaf(q2.x, k4.x, s[0][0]);
                s[0][1] = fmaf(q2.x, k4.y, s[0][1]);
                s[0][2] = fmaf(q2.x, k4.z, s[0][2]);
                s[0][3] = fmaf(q2.x, k4.w, s[0][3]);
                s[1][0] = fmaf(q2.y, k4.x, s[1][0]);
                s[1][1] = fmaf(q2.y, k4.y, s[1][1]);
                s[1][2] = fmaf(q2.y, k4.z, s[1][2]);
                s[1][3] = fmaf(q2.y, k4.w, s[1][3]);
            }
#pragma unroll
            for (int i = 0; i < 2; i++)
#pragma unroll
                for (int j = 0; j < 4; j++) s[i][j] *= sm_scale;

            if (kt == qt) {   // diagonal tile: causal mask
#pragma unroll
                for (int i = 0; i < 2; i++)
#pragma unroll
                    for (int j = 0; j < 4; j++)
                        if (tcol * 4 + j > r0 + i) s[i][j] = NEG_INF;
            }

            // ---- online softmax (per row, reduced over the 8-lane row group) ----
            float p[2][4];
#pragma unroll
            for (int i = 0; i < 2; i++) {
                float tm = fmaxf(fmaxf(s[i][0], s[i][1]), fmaxf(s[i][2], s[i][3]));
                tm = fmaxf(tm, __shfl_xor_sync(0xffffffffu, tm, 1));
                tm = fmaxf(tm, __shfl_xor_sync(0xffffffffu, tm, 2));
                tm = fmaxf(tm, __shfl_xor_sync(0xffffffffu, tm, 4));
                const float mnew  = fmaxf(m[i], tm);
                const float alpha = __expf(m[i] - mnew);
                float sum = 0.f;
#pragma unroll
                for (int j = 0; j < 4; j++) {
                    p[i][j] = __expf(s[i][j] - mnew);
                    sum += p[i][j];
                }
                sum += __shfl_xor_sync(0xffffffffu, sum, 1);
                sum += __shfl_xor_sync(0xffffffffu, sum, 2);
                sum += __shfl_xor_sync(0xffffffffu, sum, 4);
                l[i] = l[i] * alpha + sum;
#pragma unroll
                for (int d = 0; d < 8; d++) o[i][d] *= alpha;
                m[i] = mnew;
            }

            // write P (rows r0,r0+1 for cols tcol*4..+4) — consumed within this warp
#pragma unroll
            for (int j = 0; j < 4; j++)
                *(float2*)&Ps[tcol * 4 + j][r0] = make_float2(p[0][j], p[1][j]);
            __syncwarp();

            // ---- O += P V (outer product over s) ----
#pragma unroll 8
            for (int sx = 0; sx < BN; sx++) {
                const float2 p2 = *(const float2*)&Ps[sx][r0];
                const float4 va = *(const float4*)&Vs[sx][tcol * 8];
                const float4 vb = *(const float4*)&Vs[sx][tcol * 8 + 4];
                o[0][0] = fmaf(p2.x, va.x, o[0][0]);
                o[0][1] = fmaf(p2.x, va.y, o[0][1]);
                o[0][2] = fmaf(p2.x, va.z, o[0][2]);
                o[0][3] = fmaf(p2.x, va.w, o[0][3]);
                o[0][4] = fmaf(p2.x, vb.x, o[0][4]);
                o[0][5] = fmaf(p2.x, vb.y, o[0][5]);
                o[0][6] = fmaf(p2.x, vb.z, o[0][6]);
                o[0][7] = fmaf(p2.x, vb.w, o[0][7]);
                o[1][0] = fmaf(p2.y, va.x, o[1][0]);
                o[1][1] = fmaf(p2.y, va.y, o[1][1]);
                o[1][2] = fmaf(p2.y, va.z, o[1][2]);
                o[1][3] = fmaf(p2.y, va.w, o[1][3]);
                o[1][4] = fmaf(p2.y, vb.x, o[1][4]);
                o[1][5] = fmaf(p2.y, vb.y, o[1][5]);
                o[1][6] = fmaf(p2.y, vb.z, o[1][6]);
                o[1][7] = fmaf(p2.y, vb.w, o[1][7]);
            }
        }

        // epilogue: normalize + store
#pragma unroll
        for (int i = 0; i < 2; i++) {
            const float inv = __fdividef(1.f, l[i]);
            const int row = qt * BM + r0 + i;
            float4 oa, ob;
            oa.x = o[i][0] * inv; oa.y = o[i][1] * inv;
            oa.z = o[i][2] * inv; oa.w = o[i][3] * inv;
            ob.x = o[i][4] * inv; ob.y = o[i][5] * inv;
            ob.z = o[i][6] * inv; ob.w = o[i][7] * inv;
            float4* op = (float4*)(out + base + (size_t)row * HDIM + tcol * 8);
            op[0] = oa;
            op[1] = ob;
        }
    }
}

extern "C" void kernel_launch(void* const* d_in, const int* in_sizes, int n_in,
                              void* d_out, int out_size) {
    const float* x  = (const float*)d_in[0];
    const float* Wq = (const float*)d_in[1];
    const float* Wk = (const float*)d_in[2];
    const float* Wv = (const float*)d_in[3];
    float* out = (float*)d_out;

    qkv_proj<<<(BATCH * SEQ) / 16, 192>>>(x, Wq, Wk, Wv);
    flash_fwd<<<BATCH * PAIRS, 128>>>(out);
}

// round 7
// speedup vs baseline: 2.8704x; 1.6239x over previous
#include <cuda_runtime.h>
#include <cstdint>

#define BATCH 4
#define SEQ   4096
#define EMB   384
#define HDIM  64
#define BM    64
#define BN    128
#define NTQ   (SEQ / BM)          // 64 q tiles per batch
#define KST   68                  // padded row stride (floats)

// smem layout (float offsets)
#define KS_OFF 0
#define VS_OFF (2 * BN * KST)                 // 17408
#define QS_OFF (4 * BN * KST)                 // 34816
#define PS_OFF (QS_OFF + BM * KST)            // 39168
#define SMEM_FLOATS (PS_OFF + BN * KST)       // 47872
#define SMEM_BYTES  (SMEM_FLOATS * 4)         // 191488

__device__ float g_q[BATCH * SEQ * HDIM];
__device__ float g_k[BATCH * SEQ * HDIM];
__device__ float g_v[BATCH * SEQ * HDIM];

__device__ __forceinline__ void cp16(unsigned int saddr, const void* gptr) {
    asm volatile("cp.async.cg.shared.global [%0], [%1], 16;" :: "r"(saddr), "l"(gptr));
}
__device__ __forceinline__ void cp_commit() {
    asm volatile("cp.async.commit_group;");
}

// ---------------- fused QKV projection ----------------
__global__ __launch_bounds__(192) void qkv_proj(const float* __restrict__ x,
                                                const float* __restrict__ Wq,
                                                const float* __restrict__ Wk,
                                                const float* __restrict__ Wv) {
    __shared__ float4 xs4[16 * 96];
    const int tid = threadIdx.x;
    const size_t row0 = (size_t)blockIdx.x * 16;

    const float4* xsrc = (const float4*)(x + row0 * EMB);
#pragma unroll
    for (int i = 0; i < 8; i++) xs4[tid + i * 192] = xsrc[tid + i * 192];
    __syncthreads();

    const int mat = tid >> 6;
    const int col = tid & 63;
    const float* W = (mat == 0) ? Wq : (mat == 1 ? Wk : Wv);
    float* dst     = (mat == 0) ? g_q : (mat == 1 ? g_k : g_v);

    float acc[16];
#pragma unroll
    for (int r = 0; r < 16; r++) acc[r] = 0.f;

#pragma unroll 4
    for (int e4 = 0; e4 < 96; e4++) {
        const float w0 = W[(e4 * 4 + 0) * HDIM + col];
        const float w1 = W[(e4 * 4 + 1) * HDIM + col];
        const float w2 = W[(e4 * 4 + 2) * HDIM + col];
        const float w3 = W[(e4 * 4 + 3) * HDIM + col];
#pragma unroll
        for (int r = 0; r < 16; r++) {
            const float4 xv = xs4[r * 96 + e4];
            acc[r] = fmaf(xv.x, w0, fmaf(xv.y, w1, fmaf(xv.z, w2, fmaf(xv.w, w3, acc[r]))));
        }
    }
#pragma unroll
    for (int r = 0; r < 16; r++)
        dst[(row0 + r) * HDIM + col] = acc[r];
}

// ---------------- causal flash attention, register-tiled, cp.async pipelined ----------------
// 256 threads: trow=tid>>4 (16), tcol=tid&15 (16).
// S phase: rows 4*trow..+4, cols jj*16+tcol (jj<8)  -> 4x8 tile, dot-product over k.
// PV phase: same rows; dims (tcol&7)*8..+8; sx half selected by tcol>>3; combined via shfl_xor 8.
__global__ __launch_bounds__(256) void flash_fwd(float* __restrict__ out) {
    extern __shared__ float sm[];
    const int tid  = threadIdx.x;
    const int b    = blockIdx.x & 3;
    const int p    = blockIdx.x >> 2;      // 0..31 -> pair (63-p, p)
    const int trow = tid >> 4;
    const int tcol = tid & 15;
    const int r0   = trow * 4;
    const int sx0  = (tcol >> 3) * 64;     // PV sx half
    const int dmb  = (tcol & 7) * 8;       // PV dim base
    const float NEG_INF = __int_as_float(0xff800000);
    const size_t base = (size_t)b * SEQ * HDIM;
    const unsigned int smb = (unsigned int)__cvta_generic_to_shared(sm);

    for (int which = 0; which < 2; which++) {
        const int qt  = which ? p : (63 - p);
        const int nkt = (qt >> 1) + 1;

        __syncthreads();   // prior q-tile fully consumed (Qs/Ps/stages reusable)

        // stage Q tile (scaled by 1/8)
        {
            const float4* qsrc = (const float4*)(g_q + base + (size_t)qt * BM * HDIM);
#pragma unroll
            for (int j = 0; j < 4; j++) {
                const int idx = tid + 256 * j;       // 0..1023
                const int row = idx >> 4, c4 = idx & 15;
                float4 v = qsrc[idx];
                v.x *= 0.125f; v.y *= 0.125f; v.z *= 0.125f; v.w *= 0.125f;
                *(float4*)&sm[QS_OFF + row * KST + c4 * 4] = v;
            }
        }

        float o[4][8];
#pragma unroll
        for (int i = 0; i < 4; i++)
#pragma unroll
            for (int d = 0; d < 8; d++) o[i][d] = 0.f;
        float m[4] = {NEG_INF, NEG_INF, NEG_INF, NEG_INF};
        float l[4] = {0.f, 0.f, 0.f, 0.f};

        // prefetch KV tile 0 -> stage 0
        {
            const float* kg = g_k + base;
            const float* vg = g_v + base;
#pragma unroll
            for (int j = 0; j < 8; j++) {
                const int idx = tid + 256 * j;        // 0..2047
                const int row = idx >> 4, c4 = idx & 15;
                cp16(smb + (unsigned int)((KS_OFF + row * KST + c4 * 4) << 2), kg + idx * 4);
                cp16(smb + (unsigned int)((VS_OFF + row * KST + c4 * 4) << 2), vg + idx * 4);
            }
            cp_commit();
        }

        for (int kt = 0; kt < nkt; kt++) {
            const int cur = kt & 1;
            __syncthreads();   // everyone done reading the stage we're about to refill

            if (kt + 1 < nkt) {
                const int nstage = cur ^ 1;
                const float* kg = g_k + base + (size_t)(kt + 1) * BN * HDIM;
                const float* vg = g_v + base + (size_t)(kt + 1) * BN * HDIM;
#pragma unroll
                for (int j = 0; j < 8; j++) {
                    const int idx = tid + 256 * j;
                    const int row = idx >> 4, c4 = idx & 15;
                    cp16(smb + (unsigned int)((KS_OFF + (nstage * BN + row) * KST + c4 * 4) << 2), kg + idx * 4);
                    cp16(smb + (unsigned int)((VS_OFF + (nstage * BN + row) * KST + c4 * 4) << 2), vg + idx * 4);
                }
                cp_commit();
                asm volatile("cp.async.wait_group 1;");
            } else {
                asm volatile("cp.async.wait_group 0;");
            }
            __syncthreads();

            // ---- S = Q K^T, dot-product over k in chunks of 4 ----
            float s[4][8];
#pragma unroll
            for (int i = 0; i < 4; i++)
#pragma unroll
                for (int j = 0; j < 8; j++) s[i][j] = 0.f;

            const float* Kst = sm + KS_OFF + cur * BN * KST;
#pragma unroll 4
            for (int k4 = 0; k4 < 16; k4++) {
                float4 q[4];
#pragma unroll
                for (int i = 0; i < 4; i++)
                    q[i] = *(const float4*)&sm[QS_OFF + (r0 + i) * KST + k4 * 4];
#pragma unroll
                for (int jj = 0; jj < 8; jj++) {
                    const float4 kv = *(const float4*)&Kst[(jj * 16 + tcol) * KST + k4 * 4];
#pragma unroll
                    for (int i = 0; i < 4; i++) {
                        s[i][jj] = fmaf(q[i].x, kv.x,
                                   fmaf(q[i].y, kv.y,
                                   fmaf(q[i].z, kv.z,
                                   fmaf(q[i].w, kv.w, s[i][jj]))));
                    }
                }
            }

            if (kt == nkt - 1) {  // causal mask on the last (diagonal-crossing) tile
#pragma unroll
                for (int i = 0; i < 4; i++) {
                    const int row = qt * BM + r0 + i;
#pragma unroll
                    for (int jj = 0; jj < 8; jj++)
                        if (kt * BN + jj * 16 + tcol > row) s[i][jj] = NEG_INF;
                }
            }

            // ---- online softmax (row group = 16 lanes sharing trow) ----
#pragma unroll
            for (int i = 0; i < 4; i++) {
                float tm = s[i][0];
#pragma unroll
                for (int jj = 1; jj < 8; jj++) tm = fmaxf(tm, s[i][jj]);
                tm = fmaxf(tm, __shfl_xor_sync(0xffffffffu, tm, 1));
                tm = fmaxf(tm, __shfl_xor_sync(0xffffffffu, tm, 2));
                tm = fmaxf(tm, __shfl_xor_sync(0xffffffffu, tm, 4));
                tm = fmaxf(tm, __shfl_xor_sync(0xffffffffu, tm, 8));
                const float mnew  = fmaxf(m[i], tm);
                const float alpha = __expf(m[i] - mnew);
                float sum = 0.f;
#pragma unroll
                for (int jj = 0; jj < 8; jj++) {
                    s[i][jj] = __expf(s[i][jj] - mnew);
                    sum += s[i][jj];
                }
                sum += __shfl_xor_sync(0xffffffffu, sum, 1);
                sum += __shfl_xor_sync(0xffffffffu, sum, 2);
                sum += __shfl_xor_sync(0xffffffffu, sum, 4);
                sum += __shfl_xor_sync(0xffffffffu, sum, 8);
                l[i] = l[i] * alpha + sum;
                m[i] = mnew;
#pragma unroll
                for (int d = 0; d < 8; d++) o[i][d] *= alpha;
            }

            // write P transposed: Ps[col][row]
#pragma unroll
            for (int jj = 0; jj < 8; jj++) {
                float4 pv = make_float4(s[0][jj], s[1][jj], s[2][jj], s[3][jj]);
                *(float4*)&sm[PS_OFF + (jj * 16 + tcol) * KST + r0] = pv;
            }
            __syncthreads();

            // ---- O += P V over this thread's sx half ----
            const float* Vst = sm + VS_OFF + cur * BN * KST;
#pragma unroll 8
            for (int u = 0; u < 64; u++) {
                const int sx = sx0 + u;
                const float4 p4 = *(const float4*)&sm[PS_OFF + sx * KST + r0];
                const float4 va = *(const float4*)&Vst[sx * KST + dmb];
                const float4 vb = *(const float4*)&Vst[sx * KST + dmb + 4];
#pragma unroll
                for (int i = 0; i < 4; i++) {
                    const float pi = (i == 0) ? p4.x : (i == 1) ? p4.y : (i == 2) ? p4.z : p4.w;
                    o[i][0] = fmaf(pi, va.x, o[i][0]);
                    o[i][1] = fmaf(pi, va.y, o[i][1]);
                    o[i][2] = fmaf(pi, va.z, o[i][2]);
                    o[i][3] = fmaf(pi, va.w, o[i][3]);
                    o[i][4] = fmaf(pi, vb.x, o[i][4]);
                    o[i][5] = fmaf(pi, vb.y, o[i][5]);
                    o[i][6] = fmaf(pi, vb.z, o[i][6]);
                    o[i][7] = fmaf(pi, vb.w, o[i][7]);
                }
            }
        }

        // combine the two sx halves (partner lane = tcol ^ 8, same warp) + store
#pragma unroll
        for (int i = 0; i < 4; i++)
#pragma unroll
            for (int d = 0; d < 8; d++)
                o[i][d] += __shfl_xor_sync(0xffffffffu, o[i][d], 8);

        if ((tcol & 8) == 0) {
#pragma unroll
            for (int i = 0; i < 4; i++) {
                const float inv = __fdividef(1.f, l[i]);
                const int row = qt * BM + r0 + i;
                float4 oa, ob;
                oa.x = o[i][0] * inv; oa.y = o[i][1] * inv;
                oa.z = o[i][2] * inv; oa.w = o[i][3] * inv;
                ob.x = o[i][4] * inv; ob.y = o[i][5] * inv;
                ob.z = o[i][6] * inv; ob.w = o[i][7] * inv;
                float4* op = (float4*)(out + base + (size_t)row * HDIM + dmb);
                op[0] = oa;
                op[1] = ob;
            }
        }
    }
}

extern "C" void kernel_launch(void* const* d_in, const int* in_sizes, int n_in,
                              void* d_out, int out_size) {
    const float* x  = (const float*)d_in[0];
    const float* Wq = (const float*)d_in[1];
    const float* Wk = (const float*)d_in[2];
    const float* Wv = (const float*)d_in[3];
    float* out = (float*)d_out;

    // idempotent; first harness call happens outside graph capture
    cudaFuncSetAttribute(flash_fwd, cudaFuncAttributeMaxDynamicSharedMemorySize, SMEM_BYTES);

    qkv_proj<<<(BATCH * SEQ) / 16, 192>>>(x, Wq, Wk, Wv);
    flash_fwd<<<BATCH * 32, 256, SMEM_BYTES>>>(out);
}